// round 5
// baseline (speedup 1.0000x reference)
#include <cuda_runtime.h>
#include <math_constants.h>

#define NPIX_MAX (32 * 128 * 2048)
#define TB   256
#define OCC  4
#define GRID (148 * OCC)   // 592: <= 4 CTAs/SM on 148- or 152-SM parts

__device__ float        g_gray[NPIX_MAX];
__device__ unsigned int g_min_bits;
__device__ unsigned int g_max_bits;
__device__ unsigned int g_hist[256];
__device__ float        g_thresh;
__device__ unsigned int g_bar;

__device__ __forceinline__ unsigned int f_enc(float f) {
    unsigned int u = __float_as_uint(f);
    return (u & 0x80000000u) ? ~u : (u | 0x80000000u);
}
__device__ __forceinline__ float f_dec(unsigned int e) {
    unsigned int u = (e & 0x80000000u) ? (e & 0x7FFFFFFFu) : ~e;
    return __uint_as_float(u);
}
__device__ __forceinline__ float gray_of(float r, float g, float b) {
    return fmaf(0.1140f, b, fmaf(0.5870f, g, __fmul_rn(0.2989f, r)));
}

// one atomicAdd per block; monotonic counter (reset by init_kernel per replay)
__device__ __forceinline__ void grid_barrier(unsigned int target) {
    __syncthreads();
    if (threadIdx.x == 0) {
        __threadfence();                       // release: publish our writes
        atomicAdd(&g_bar, 1u);
        while (*((volatile unsigned int*)&g_bar) < target) __nanosleep(64);
        __threadfence();                       // acquire side
    }
    __syncthreads();
}

// ---------------- K0: reset state (inside graph, every replay) -------------
__global__ void init_kernel() {
    int t = threadIdx.x;
    if (t < 256) g_hist[t] = 0u;
    if (t == 0) {
        g_min_bits = 0xFFFFFFFFu;
        g_max_bits = 0x00000000u;
        g_thresh   = 0.0f;
        g_bar      = 0u;
    }
}

struct SharedU {
    union {
        float4       stage[TB * 3];     // 12 KB: phases 1 & 4
        unsigned int hist[256 * 8];     //  8 KB: phase 2
        struct {
            float c[256], w1[256], s1[256], w2[256], s2[256], bv[256];
            int bi[256];
        } otsu;                          //  7 KB: phase 3
    };
};

// ---------------- fused persistent kernel ----------------------------------
__global__ void __launch_bounds__(TB, OCC)
fused_kernel(const float* __restrict__ in, float* __restrict__ out, int npix) {
    __shared__ SharedU sh;
    __shared__ float smin[8], smax[8];

    const int t       = threadIdx.x;
    const int G       = gridDim.x;
    const int ngroups = npix >> 2;
    const int nf4     = ngroups * 3;
    const int ntiles  = (ngroups + TB - 1) / TB;
    const int gstride = G * TB;

    // ================= phase 1: gray + min/max =================
    {
        const float4* __restrict__ in4 = (const float4*)in;
        float4* __restrict__ gr4 = (float4*)g_gray;
        float lmin = CUDART_INF_F, lmax = -CUDART_INF_F;

        for (int tile = blockIdx.x; tile < ntiles; tile += G) {
            const int gbase = tile * TB;
            const int fbase = gbase * 3;
            #pragma unroll
            for (int j = 0; j < 3; j++) {
                int idx = t + j * TB;
                if (fbase + idx < nf4) sh.stage[idx] = in4[fbase + idx];
            }
            __syncthreads();
            const int g = gbase + t;
            if (g < ngroups) {
                float4 a = sh.stage[3 * t + 0];
                float4 b = sh.stage[3 * t + 1];
                float4 c = sh.stage[3 * t + 2];
                float g0 = gray_of(a.x, a.y, a.z);
                float g1 = gray_of(a.w, b.x, b.y);
                float g2 = gray_of(b.z, b.w, c.x);
                float g3 = gray_of(c.y, c.z, c.w);
                gr4[g] = make_float4(g0, g1, g2, g3);
                lmin = fminf(lmin, fminf(fminf(g0, g1), fminf(g2, g3)));
                lmax = fmaxf(lmax, fmaxf(fmaxf(g0, g1), fmaxf(g2, g3)));
            }
            __syncthreads();
        }
        for (int p = (ngroups << 2) + blockIdx.x * TB + t; p < npix; p += gstride) {
            float gg = gray_of(in[3 * p], in[3 * p + 1], in[3 * p + 2]);
            g_gray[p] = gg;
            lmin = fminf(lmin, gg);
            lmax = fmaxf(lmax, gg);
        }

        for (int o = 16; o; o >>= 1) {
            lmin = fminf(lmin, __shfl_xor_sync(0xFFFFFFFFu, lmin, o));
            lmax = fmaxf(lmax, __shfl_xor_sync(0xFFFFFFFFu, lmax, o));
        }
        int wid = t >> 5, lid = t & 31;
        if (lid == 0) { smin[wid] = lmin; smax[wid] = lmax; }
        __syncthreads();
        if (t == 0) {
            float bmin = smin[0], bmax = smax[0];
            #pragma unroll
            for (int i = 1; i < (TB >> 5); i++) {
                bmin = fminf(bmin, smin[i]);
                bmax = fmaxf(bmax, smax[i]);
            }
            atomicMin(&g_min_bits, f_enc(bmin));
            atomicMax(&g_max_bits, f_enc(bmax));
        }
    }

    grid_barrier(1u * G);

    // ================= phase 2: 256-bin histogram =================
    {
        for (int i = t; i < 256 * 8; i += TB) sh.hist[i] = 0u;
        __syncthreads();

        const float vmin = f_dec(*((volatile unsigned int*)&g_min_bits));
        const float vmax = f_dec(*((volatile unsigned int*)&g_max_bits));
        const float scale = 256.0f / (vmax - vmin);

        unsigned int* my = sh.hist + ((t >> 5) & 7) * 256;
        const float4* __restrict__ gr4 = (const float4*)g_gray;

        for (int g = blockIdx.x * TB + t; g < ngroups; g += gstride) {
            float4 v = __ldcg(&gr4[g]);
            int b0 = min(255, max(0, (int)((v.x - vmin) * scale)));
            int b1 = min(255, max(0, (int)((v.y - vmin) * scale)));
            int b2 = min(255, max(0, (int)((v.z - vmin) * scale)));
            int b3 = min(255, max(0, (int)((v.w - vmin) * scale)));
            atomicAdd(&my[b0], 1u);
            atomicAdd(&my[b1], 1u);
            atomicAdd(&my[b2], 1u);
            atomicAdd(&my[b3], 1u);
        }
        for (int p = (ngroups << 2) + blockIdx.x * TB + t; p < npix; p += gstride) {
            float gg = __ldcg(&g_gray[p]);
            int b = min(255, max(0, (int)((gg - vmin) * scale)));
            atomicAdd(&my[b], 1u);
        }
        __syncthreads();
        for (int i = t; i < 256; i += TB) {
            unsigned int s = 0;
            #pragma unroll
            for (int r = 0; r < 8; r++) s += sh.hist[r * 256 + i];
            if (s) atomicAdd(&g_hist[i], s);
        }
    }

    grid_barrier(2u * G);

    // ================= phase 3: Otsu (block 0 only) =================
    if (blockIdx.x == 0) {
        const float vmin = f_dec(g_min_bits);
        const float vmax = f_dec(g_max_bits);
        const float step = __fmul_rn(__fadd_rn(vmax, -vmin), 1.0f / 256.0f);

        float e0 = __fadd_rn(vmin, __fmul_rn(step, (float)t));
        float e1 = (t == 255) ? vmax : __fadd_rn(vmin, __fmul_rn(step, (float)(t + 1)));
        float ct = __fmul_rn(__fadd_rn(e0, e1), 0.5f);
        sh.otsu.c[t] = ct;

        float hv = (float)__ldcg(&g_hist[t]);
        float hc = __fmul_rn(hv, ct);
        sh.otsu.w1[t] = hv; sh.otsu.s1[t] = hc;
        sh.otsu.w2[t] = hv; sh.otsu.s2[t] = hc;
        __syncthreads();

        #pragma unroll
        for (int s = 1; s < 256; s <<= 1) {
            float aw1 = (t >= s)      ? sh.otsu.w1[t - s] : 0.0f;
            float as1 = (t >= s)      ? sh.otsu.s1[t - s] : 0.0f;
            float aw2 = (t + s < 256) ? sh.otsu.w2[t + s] : 0.0f;
            float as2 = (t + s < 256) ? sh.otsu.s2[t + s] : 0.0f;
            __syncthreads();
            sh.otsu.w1[t] = __fadd_rn(sh.otsu.w1[t], aw1);
            sh.otsu.s1[t] = __fadd_rn(sh.otsu.s1[t], as1);
            sh.otsu.w2[t] = __fadd_rn(sh.otsu.w2[t], aw2);
            sh.otsu.s2[t] = __fadd_rn(sh.otsu.s2[t], as2);
            __syncthreads();
        }

        float v = -CUDART_INF_F;
        if (t < 255) {
            float m1 = sh.otsu.s1[t] / fmaxf(sh.otsu.w1[t], 1.0f);
            float m2 = sh.otsu.s2[t + 1] / fmaxf(sh.otsu.w2[t + 1], 1.0f);
            float d = __fadd_rn(m1, -m2);
            v = __fmul_rn(__fmul_rn(sh.otsu.w1[t], sh.otsu.w2[t + 1]), __fmul_rn(d, d));
        }
        sh.otsu.bv[t] = v; sh.otsu.bi[t] = t;
        __syncthreads();
        for (int s = 128; s; s >>= 1) {
            if (t < s) {
                float ov = sh.otsu.bv[t + s]; int oi = sh.otsu.bi[t + s];
                if (ov > sh.otsu.bv[t] || (ov == sh.otsu.bv[t] && oi < sh.otsu.bi[t])) {
                    sh.otsu.bv[t] = ov; sh.otsu.bi[t] = oi;
                }
            }
            __syncthreads();
        }
        if (t == 0) g_thresh = sh.otsu.c[sh.otsu.bi[0]];
    }

    grid_barrier(3u * G);

    // ================= phase 4: binarize + tile =================
    {
        const float thr = *((volatile float*)&g_thresh);
        const float4* __restrict__ gr4 = (const float4*)g_gray;
        float4* __restrict__ o4 = (float4*)out;

        for (int tile = blockIdx.x; tile < ntiles; tile += G) {
            const int gbase = tile * TB;
            const int g = gbase + t;
            if (g < ngroups) {
                float4 v = __ldcg(&gr4[g]);
                float b0 = (v.x > thr) ? 1.0f : 0.0f;
                float b1 = (v.y > thr) ? 1.0f : 0.0f;
                float b2 = (v.z > thr) ? 1.0f : 0.0f;
                float b3 = (v.w > thr) ? 1.0f : 0.0f;
                sh.stage[3 * t + 0] = make_float4(b0, b0, b0, b1);
                sh.stage[3 * t + 1] = make_float4(b1, b1, b2, b2);
                sh.stage[3 * t + 2] = make_float4(b2, b3, b3, b3);
            }
            __syncthreads();
            const int fbase = gbase * 3;
            #pragma unroll
            for (int j = 0; j < 3; j++) {
                int idx = t + j * TB;
                if (fbase + idx < nf4) o4[fbase + idx] = sh.stage[idx];
            }
            __syncthreads();
        }
        for (int p = (ngroups << 2) + blockIdx.x * TB + t; p < npix; p += gstride) {
            float b = (__ldcg(&g_gray[p]) > thr) ? 1.0f : 0.0f;
            out[3 * p + 0] = b;
            out[3 * p + 1] = b;
            out[3 * p + 2] = b;
        }
    }
}

// ---------------- launch ---------------------------------------------------
extern "C" void kernel_launch(void* const* d_in, const int* in_sizes, int n_in,
                              void* d_out, int out_size) {
    const float* in = (const float*)d_in[0];
    float* out = (float*)d_out;
    int npix = in_sizes[0] / 3;

    init_kernel<<<1, 256>>>();
    fused_kernel<<<GRID, TB>>>(in, out, npix);
}

// round 7
// speedup vs baseline: 1.0931x; 1.0931x over previous
#include <cuda_runtime.h>
#include <math_constants.h>

#define NPIX_MAX (32 * 128 * 2048)
#define TB 256

__device__ float        g_gray[NPIX_MAX];
__device__ unsigned int g_min_bits;
__device__ unsigned int g_max_bits;
__device__ unsigned int g_hist[256];

__device__ __forceinline__ unsigned int f_enc(float f) {
    unsigned int u = __float_as_uint(f);
    return (u & 0x80000000u) ? ~u : (u | 0x80000000u);
}
__device__ __forceinline__ float f_dec(unsigned int e) {
    unsigned int u = (e & 0x80000000u) ? (e & 0x7FFFFFFFu) : ~e;
    return __uint_as_float(u);
}
__device__ __forceinline__ float gray_of(float r, float g, float b) {
    return fmaf(0.1140f, b, fmaf(0.5870f, g, __fmul_rn(0.2989f, r)));
}

// ---------------- K0: reset state (inside graph, every replay) -------------
__global__ void init_kernel() {
    int t = threadIdx.x;
    if (t < 256) g_hist[t] = 0u;
    if (t == 0) {
        g_min_bits = 0xFFFFFFFFu;
        g_max_bits = 0x00000000u;
    }
}

// ---------------- K1: gray + min/max (smem-staged coalesced loads) ---------
__global__ void gray_minmax_kernel(const float* __restrict__ in, int npix) {
    __shared__ float4 stage[TB * 3];            // 12 KB
    const int ngroups = npix >> 2;
    const int nf4     = ngroups * 3;
    const int ntiles  = (ngroups + TB - 1) / TB;
    const float4* __restrict__ in4 = (const float4*)in;
    float4* __restrict__ gr4 = (float4*)g_gray;
    const int t = threadIdx.x;

    float lmin = CUDART_INF_F, lmax = -CUDART_INF_F;

    for (int tile = blockIdx.x; tile < ntiles; tile += gridDim.x) {
        const int gbase = tile * TB;
        const int fbase = gbase * 3;
        #pragma unroll
        for (int j = 0; j < 3; j++) {
            int idx = t + j * TB;
            if (fbase + idx < nf4) stage[idx] = in4[fbase + idx];
        }
        __syncthreads();
        const int g = gbase + t;
        if (g < ngroups) {
            float4 a = stage[3 * t + 0];
            float4 b = stage[3 * t + 1];
            float4 c = stage[3 * t + 2];
            float g0 = gray_of(a.x, a.y, a.z);
            float g1 = gray_of(a.w, b.x, b.y);
            float g2 = gray_of(b.z, b.w, c.x);
            float g3 = gray_of(c.y, c.z, c.w);
            gr4[g] = make_float4(g0, g1, g2, g3);
            lmin = fminf(lmin, fminf(fminf(g0, g1), fminf(g2, g3)));
            lmax = fmaxf(lmax, fmaxf(fmaxf(g0, g1), fmaxf(g2, g3)));
        }
        __syncthreads();
    }
    const int stride = gridDim.x * blockDim.x;
    for (int p = (ngroups << 2) + blockIdx.x * blockDim.x + t; p < npix; p += stride) {
        float gg = gray_of(in[3 * p], in[3 * p + 1], in[3 * p + 2]);
        g_gray[p] = gg;
        lmin = fminf(lmin, gg);
        lmax = fmaxf(lmax, gg);
    }

    for (int o = 16; o; o >>= 1) {
        lmin = fminf(lmin, __shfl_xor_sync(0xFFFFFFFFu, lmin, o));
        lmax = fmaxf(lmax, __shfl_xor_sync(0xFFFFFFFFu, lmax, o));
    }
    __shared__ float smin[8], smax[8];
    int wid = t >> 5, lid = t & 31;
    if (lid == 0) { smin[wid] = lmin; smax[wid] = lmax; }
    __syncthreads();
    if (t == 0) {
        float bmin = smin[0], bmax = smax[0];
        #pragma unroll
        for (int i = 1; i < (TB >> 5); i++) {
            bmin = fminf(bmin, smin[i]);
            bmax = fmaxf(bmax, smax[i]);
        }
        atomicMin(&g_min_bits, f_enc(bmin));
        atomicMax(&g_max_bits, f_enc(bmax));
    }
}

// ---------------- K2: 256-bin histogram ------------------------------------
__global__ void hist_kernel(int npix) {
    __shared__ unsigned int sh[256 * 8];
    for (int i = threadIdx.x; i < 256 * 8; i += blockDim.x) sh[i] = 0u;
    __syncthreads();

    const float vmin = f_dec(g_min_bits);
    const float vmax = f_dec(g_max_bits);
    const float scale = 256.0f / (vmax - vmin);

    unsigned int* my = sh + ((threadIdx.x >> 5) & 7) * 256;
    const int ngroups = npix >> 2;
    const int stride  = gridDim.x * blockDim.x;
    const float4* __restrict__ gr4 = (const float4*)g_gray;

    for (int g = blockIdx.x * blockDim.x + threadIdx.x; g < ngroups; g += stride) {
        float4 v = gr4[g];
        int b0 = min(255, max(0, (int)((v.x - vmin) * scale)));
        int b1 = min(255, max(0, (int)((v.y - vmin) * scale)));
        int b2 = min(255, max(0, (int)((v.z - vmin) * scale)));
        int b3 = min(255, max(0, (int)((v.w - vmin) * scale)));
        atomicAdd(&my[b0], 1u);
        atomicAdd(&my[b1], 1u);
        atomicAdd(&my[b2], 1u);
        atomicAdd(&my[b3], 1u);
    }
    for (int p = (ngroups << 2) + blockIdx.x * blockDim.x + threadIdx.x; p < npix; p += stride) {
        int b = min(255, max(0, (int)((g_gray[p] - vmin) * scale)));
        atomicAdd(&my[b], 1u);
    }
    __syncthreads();
    for (int i = threadIdx.x; i < 256; i += blockDim.x) {
        unsigned int s = 0;
        #pragma unroll
        for (int r = 0; r < 8; r++) s += sh[r * 256 + i];
        if (s) atomicAdd(&g_hist[i], s);
    }
}

// -------- K3: per-block Otsu prologue + binarize + tile --------------------
struct BinShared {
    union {
        float4 stage[TB * 3];           // 12 KB (streaming)
        struct {
            float c[256], w1[256], s1[256], w2[256], s2[256], bv[256];
            int bi[256];
        } o;                             // 7 KB (prologue)
    };
};

__global__ void binarize_kernel(float* __restrict__ out, int npix) {
    __shared__ BinShared sh;
    __shared__ float s_thresh;
    const int t = threadIdx.x;

    // ---- Otsu prologue: every block computes threshold from g_hist ----
    {
        const float vmin = f_dec(g_min_bits);
        const float vmax = f_dec(g_max_bits);
        const float step = __fmul_rn(__fadd_rn(vmax, -vmin), 1.0f / 256.0f);

        float e0 = __fadd_rn(vmin, __fmul_rn(step, (float)t));
        float e1 = (t == 255) ? vmax : __fadd_rn(vmin, __fmul_rn(step, (float)(t + 1)));
        float ct = __fmul_rn(__fadd_rn(e0, e1), 0.5f);
        sh.o.c[t] = ct;

        float hv = (float)g_hist[t];
        float hc = __fmul_rn(hv, ct);
        sh.o.w1[t] = hv; sh.o.s1[t] = hc;
        sh.o.w2[t] = hv; sh.o.s2[t] = hc;
        __syncthreads();

        #pragma unroll
        for (int s = 1; s < 256; s <<= 1) {
            float aw1 = (t >= s)      ? sh.o.w1[t - s] : 0.0f;
            float as1 = (t >= s)      ? sh.o.s1[t - s] : 0.0f;
            float aw2 = (t + s < 256) ? sh.o.w2[t + s] : 0.0f;
            float as2 = (t + s < 256) ? sh.o.s2[t + s] : 0.0f;
            __syncthreads();
            sh.o.w1[t] = __fadd_rn(sh.o.w1[t], aw1);
            sh.o.s1[t] = __fadd_rn(sh.o.s1[t], as1);
            sh.o.w2[t] = __fadd_rn(sh.o.w2[t], aw2);
            sh.o.s2[t] = __fadd_rn(sh.o.s2[t], as2);
            __syncthreads();
        }

        float v = -CUDART_INF_F;
        if (t < 255) {
            float m1 = sh.o.s1[t] / fmaxf(sh.o.w1[t], 1.0f);
            float m2 = sh.o.s2[t + 1] / fmaxf(sh.o.w2[t + 1], 1.0f);
            float d = __fadd_rn(m1, -m2);
            v = __fmul_rn(__fmul_rn(sh.o.w1[t], sh.o.w2[t + 1]), __fmul_rn(d, d));
        }
        sh.o.bv[t] = v; sh.o.bi[t] = t;
        __syncthreads();
        for (int s = 128; s; s >>= 1) {
            if (t < s) {
                float ov = sh.o.bv[t + s]; int oi = sh.o.bi[t + s];
                if (ov > sh.o.bv[t] || (ov == sh.o.bv[t] && oi < sh.o.bi[t])) {
                    sh.o.bv[t] = ov; sh.o.bi[t] = oi;
                }
            }
            __syncthreads();
        }
        if (t == 0) s_thresh = sh.o.c[sh.o.bi[0]];
        __syncthreads();
    }

    // ---- streaming binarize + tile ----
    const float thr = s_thresh;
    const int ngroups = npix >> 2;
    const int nf4     = ngroups * 3;
    const int ntiles  = (ngroups + TB - 1) / TB;
    const float4* __restrict__ gr4 = (const float4*)g_gray;
    float4* __restrict__ o4 = (float4*)out;

    for (int tile = blockIdx.x; tile < ntiles; tile += gridDim.x) {
        const int gbase = tile * TB;
        const int g = gbase + t;
        __syncthreads();
        if (g < ngroups) {
            float4 v = gr4[g];
            float b0 = (v.x > thr) ? 1.0f : 0.0f;
            float b1 = (v.y > thr) ? 1.0f : 0.0f;
            float b2 = (v.z > thr) ? 1.0f : 0.0f;
            float b3 = (v.w > thr) ? 1.0f : 0.0f;
            sh.stage[3 * t + 0] = make_float4(b0, b0, b0, b1);
            sh.stage[3 * t + 1] = make_float4(b1, b1, b2, b2);
            sh.stage[3 * t + 2] = make_float4(b2, b3, b3, b3);
        }
        __syncthreads();
        const int fbase = gbase * 3;
        #pragma unroll
        for (int j = 0; j < 3; j++) {
            int idx = t + j * TB;
            if (fbase + idx < nf4) o4[fbase + idx] = sh.stage[idx];
        }
    }
    const int stride = gridDim.x * blockDim.x;
    for (int p = (ngroups << 2) + blockIdx.x * blockDim.x + t; p < npix; p += stride) {
        float b = (g_gray[p] > thr) ? 1.0f : 0.0f;
        out[3 * p + 0] = b;
        out[3 * p + 1] = b;
        out[3 * p + 2] = b;
    }
}

// ---------------- launch ---------------------------------------------------
extern "C" void kernel_launch(void* const* d_in, const int* in_sizes, int n_in,
                              void* d_out, int out_size) {
    const float* in = (const float*)d_in[0];
    float* out = (float*)d_out;
    int npix = in_sizes[0] / 3;

    const int GRID = 148 * 8;

    init_kernel<<<1, 256>>>();
    gray_minmax_kernel<<<GRID, TB>>>(in, npix);
    hist_kernel<<<GRID, TB>>>(npix);
    binarize_kernel<<<GRID, TB>>>(out, npix);
}

// round 8
// speedup vs baseline: 1.1814x; 1.0808x over previous
#include <cuda_runtime.h>
#include <math_constants.h>

#define NPIX_MAX (32 * 128 * 2048)
#define TB 256

__device__ float        g_gray[NPIX_MAX];
__device__ unsigned int g_min_bits;
__device__ unsigned int g_max_bits;
__device__ unsigned int g_hist[256];

__device__ __forceinline__ unsigned int f_enc(float f) {
    unsigned int u = __float_as_uint(f);
    return (u & 0x80000000u) ? ~u : (u | 0x80000000u);
}
__device__ __forceinline__ float f_dec(unsigned int e) {
    unsigned int u = (e & 0x80000000u) ? (e & 0x7FFFFFFFu) : ~e;
    return __uint_as_float(u);
}
__device__ __forceinline__ float gray_of(float r, float g, float b) {
    return fmaf(0.1140f, b, fmaf(0.5870f, g, __fmul_rn(0.2989f, r)));
}

// ---------------- K0: reset state (inside graph, every replay) -------------
__global__ void init_kernel() {
    int t = threadIdx.x;
    if (t < 256) g_hist[t] = 0u;
    if (t == 0) {
        g_min_bits = 0xFFFFFFFFu;
        g_max_bits = 0x00000000u;
    }
}

// ---------------- K1: gray + min/max (smem-staged coalesced loads) ---------
__global__ void gray_minmax_kernel(const float* __restrict__ in, int npix) {
    __shared__ float4 stage[TB * 3];            // 12 KB
    const int ngroups = npix >> 2;
    const int nf4     = ngroups * 3;
    const int ntiles  = (ngroups + TB - 1) / TB;
    const float4* __restrict__ in4 = (const float4*)in;
    float4* __restrict__ gr4 = (float4*)g_gray;
    const int t = threadIdx.x;

    float lmin = CUDART_INF_F, lmax = -CUDART_INF_F;

    for (int tile = blockIdx.x; tile < ntiles; tile += gridDim.x) {
        const int gbase = tile * TB;
        const int fbase = gbase * 3;
        #pragma unroll
        for (int j = 0; j < 3; j++) {
            int idx = t + j * TB;
            if (fbase + idx < nf4) stage[idx] = in4[fbase + idx];
        }
        __syncthreads();
        const int g = gbase + t;
        if (g < ngroups) {
            float4 a = stage[3 * t + 0];
            float4 b = stage[3 * t + 1];
            float4 c = stage[3 * t + 2];
            float g0 = gray_of(a.x, a.y, a.z);
            float g1 = gray_of(a.w, b.x, b.y);
            float g2 = gray_of(b.z, b.w, c.x);
            float g3 = gray_of(c.y, c.z, c.w);
            gr4[g] = make_float4(g0, g1, g2, g3);
            lmin = fminf(lmin, fminf(fminf(g0, g1), fminf(g2, g3)));
            lmax = fmaxf(lmax, fmaxf(fmaxf(g0, g1), fmaxf(g2, g3)));
        }
        __syncthreads();
    }
    const int stride = gridDim.x * blockDim.x;
    for (int p = (ngroups << 2) + blockIdx.x * blockDim.x + t; p < npix; p += stride) {
        float gg = gray_of(in[3 * p], in[3 * p + 1], in[3 * p + 2]);
        g_gray[p] = gg;
        lmin = fminf(lmin, gg);
        lmax = fmaxf(lmax, gg);
    }

    for (int o = 16; o; o >>= 1) {
        lmin = fminf(lmin, __shfl_xor_sync(0xFFFFFFFFu, lmin, o));
        lmax = fmaxf(lmax, __shfl_xor_sync(0xFFFFFFFFu, lmax, o));
    }
    __shared__ float smin[8], smax[8];
    int wid = t >> 5, lid = t & 31;
    if (lid == 0) { smin[wid] = lmin; smax[wid] = lmax; }
    __syncthreads();
    if (t == 0) {
        float bmin = smin[0], bmax = smax[0];
        #pragma unroll
        for (int i = 1; i < (TB >> 5); i++) {
            bmin = fminf(bmin, smin[i]);
            bmax = fmaxf(bmax, smax[i]);
        }
        atomicMin(&g_min_bits, f_enc(bmin));
        atomicMax(&g_max_bits, f_enc(bmax));
    }
}

// ---------------- K2: 256-bin histogram ------------------------------------
__global__ void hist_kernel(int npix) {
    __shared__ unsigned int sh[256 * 8];
    for (int i = threadIdx.x; i < 256 * 8; i += blockDim.x) sh[i] = 0u;
    __syncthreads();

    const float vmin = f_dec(g_min_bits);
    const float vmax = f_dec(g_max_bits);
    const float scale = 256.0f / (vmax - vmin);

    unsigned int* my = sh + ((threadIdx.x >> 5) & 7) * 256;
    const int ngroups = npix >> 2;
    const int stride  = gridDim.x * blockDim.x;
    const float4* __restrict__ gr4 = (const float4*)g_gray;

    for (int g = blockIdx.x * blockDim.x + threadIdx.x; g < ngroups; g += stride) {
        float4 v = gr4[g];
        int b0 = min(255, max(0, (int)((v.x - vmin) * scale)));
        int b1 = min(255, max(0, (int)((v.y - vmin) * scale)));
        int b2 = min(255, max(0, (int)((v.z - vmin) * scale)));
        int b3 = min(255, max(0, (int)((v.w - vmin) * scale)));
        atomicAdd(&my[b0], 1u);
        atomicAdd(&my[b1], 1u);
        atomicAdd(&my[b2], 1u);
        atomicAdd(&my[b3], 1u);
    }
    for (int p = (ngroups << 2) + blockIdx.x * blockDim.x + threadIdx.x; p < npix; p += stride) {
        int b = min(255, max(0, (int)((g_gray[p] - vmin) * scale)));
        atomicAdd(&my[b], 1u);
    }
    __syncthreads();
    for (int i = threadIdx.x; i < 256; i += blockDim.x) {
        unsigned int s = 0;
        #pragma unroll
        for (int r = 0; r < 8; r++) s += sh[r * 256 + i];
        if (s) atomicAdd(&g_hist[i], s);
    }
}

// -------- K3: per-block Otsu prologue + DIRECT binarize (no smem) ----------
__global__ void binarize_kernel(float* __restrict__ out, int npix) {
    __shared__ struct {
        float c[256], w1[256], s1[256], w2[256], s2[256], bv[256];
        int bi[256];
    } sh;
    __shared__ float s_thresh;
    const int t = threadIdx.x;

    // ---- Otsu prologue: every block computes threshold from g_hist ----
    {
        const float vmin = f_dec(g_min_bits);
        const float vmax = f_dec(g_max_bits);
        const float step = __fmul_rn(__fadd_rn(vmax, -vmin), 1.0f / 256.0f);

        float e0 = __fadd_rn(vmin, __fmul_rn(step, (float)t));
        float e1 = (t == 255) ? vmax : __fadd_rn(vmin, __fmul_rn(step, (float)(t + 1)));
        float ct = __fmul_rn(__fadd_rn(e0, e1), 0.5f);
        sh.c[t] = ct;

        float hv = (float)g_hist[t];
        float hc = __fmul_rn(hv, ct);
        sh.w1[t] = hv; sh.s1[t] = hc;
        sh.w2[t] = hv; sh.s2[t] = hc;
        __syncthreads();

        #pragma unroll
        for (int s = 1; s < 256; s <<= 1) {
            float aw1 = (t >= s)      ? sh.w1[t - s] : 0.0f;
            float as1 = (t >= s)      ? sh.s1[t - s] : 0.0f;
            float aw2 = (t + s < 256) ? sh.w2[t + s] : 0.0f;
            float as2 = (t + s < 256) ? sh.s2[t + s] : 0.0f;
            __syncthreads();
            sh.w1[t] = __fadd_rn(sh.w1[t], aw1);
            sh.s1[t] = __fadd_rn(sh.s1[t], as1);
            sh.w2[t] = __fadd_rn(sh.w2[t], aw2);
            sh.s2[t] = __fadd_rn(sh.s2[t], as2);
            __syncthreads();
        }

        float v = -CUDART_INF_F;
        if (t < 255) {
            float m1 = sh.s1[t] / fmaxf(sh.w1[t], 1.0f);
            float m2 = sh.s2[t + 1] / fmaxf(sh.w2[t + 1], 1.0f);
            float d = __fadd_rn(m1, -m2);
            v = __fmul_rn(__fmul_rn(sh.w1[t], sh.w2[t + 1]), __fmul_rn(d, d));
        }
        sh.bv[t] = v; sh.bi[t] = t;
        __syncthreads();
        for (int s = 128; s; s >>= 1) {
            if (t < s) {
                float ov = sh.bv[t + s]; int oi = sh.bi[t + s];
                if (ov > sh.bv[t] || (ov == sh.bv[t] && oi < sh.bi[t])) {
                    sh.bv[t] = ov; sh.bi[t] = oi;
                }
            }
            __syncthreads();
        }
        if (t == 0) s_thresh = sh.c[sh.bi[0]];
        __syncthreads();
    }

    // ---- direct streaming binarize: one out-float4 per thread-iter ----
    const float thr = s_thresh;
    const int nout4 = (npix * 3) >> 2;          // out float4 count (vector part)
    const int stride = gridDim.x * blockDim.x;
    const float* __restrict__ gray = g_gray;
    float4* __restrict__ o4 = (float4*)out;

    int f = blockIdx.x * blockDim.x + t;
    #pragma unroll 4
    for (; f < nout4; f += stride) {
        const int e0 = 4 * f;
        const int p0 = e0 / 3;            // first pixel covered
        const int r  = e0 - 3 * p0;       // 0,1,2
        float ga = __ldg(&gray[p0]);
        float gb = __ldg(&gray[p0 + 1]); // e0+3 always lands in p0+1 (p0+1 <= npix-1)
        float ba = (ga > thr) ? 1.0f : 0.0f;
        float bb = (gb > thr) ? 1.0f : 0.0f;
        // element k belongs to p0 iff (r + k) < 3
        float4 v;
        v.x = (r < 3) ? ba : bb;          // r+0
        v.y = (r < 2) ? ba : bb;          // r+1
        v.z = (r < 1) ? ba : bb;          // r+2
        v.w = bb;                          // r+3 >= 3 always
        __stcs(&o4[f], v);
    }
    // scalar tail of out elements (npix*3 not divisible by 4)
    for (int e = (nout4 << 2) + blockIdx.x * blockDim.x + t; e < npix * 3; e += stride) {
        float g = __ldg(&gray[e / 3]);
        out[e] = (g > thr) ? 1.0f : 0.0f;
    }
}

// ---------------- launch ---------------------------------------------------
extern "C" void kernel_launch(void* const* d_in, const int* in_sizes, int n_in,
                              void* d_out, int out_size) {
    const float* in = (const float*)d_in[0];
    float* out = (float*)d_out;
    int npix = in_sizes[0] / 3;

    const int GRID = 148 * 8;

    init_kernel<<<1, 256>>>();
    gray_minmax_kernel<<<GRID, TB>>>(in, npix);
    hist_kernel<<<GRID, TB>>>(npix);
    binarize_kernel<<<GRID, TB>>>(out, npix);
}